// round 1
// baseline (speedup 1.0000x reference)
#include <cuda_runtime.h>

// Dcls1d: learnable-spacing dilated conv1d.
// out[b,o,t] = bias[o] + sum_{c,k} ( wl[o,c,k]*xpad[b,c,t+lo[o,c,k]]
//                                  + wh[o,c,k]*xpad[b,c,t+lo+1] )
// where xpad is x padded by 28 on both sides, lo = floor(clip(P+28,0,55)),
// wl = w*(1-frac), wh = w*frac.
//
// Stage 1 (prep): build per-(o,c,k) tap table g_meta as float4
//                 {wl, wh, bits(lo), 0}, layout [c][o][8] (k padded to 8)
//                 so the conv kernel loads it coalesced per (c, o-tile).
// Stage 2 (conv): block = 32 o x 128 t x 1 b tile. 256 threads, 8 warps;
//                 warp handles 4 o's, lanes = 32 consecutive t, 4 t-blocks
//                 at stride 32 (conflict-free smem reads). Loop c in chunks
//                 of 8 with x windows + meta staged in smem.

#define BATCH 32
#define CIN   256
#define COUT  256
#define KTAPS 7
#define LIN   4096
#define LOUT  4097   // 4096 + 2*28 - 56 + 1
#define PADV  28

#define T_TILE  128
#define O_TILE  32
#define C_CHUNK 8
#define WIN     (T_TILE + 56)   // 184: covers t_local + lo + 1, lo <= 55

// [c][o][8] float4 tap table: 256*256*8*16 B = 8 MB (device global scratch)
__device__ float4 g_meta[(size_t)CIN * COUT * 8];

__global__ void prep_kernel(const float* __restrict__ weight,
                            const float* __restrict__ P) {
    int n = blockIdx.x * blockDim.x + threadIdx.x;     // linear index into g_meta
    if (n >= CIN * COUT * 8) return;
    int k8 = n & 7;
    int oc = n >> 3;
    int o = oc & 255;
    int c = oc >> 8;
    float4 m = make_float4(0.f, 0.f, __int_as_float(0), 0.f);
    if (k8 < KTAPS) {
        size_t wi = ((size_t)o * CIN + c) * KTAPS + k8;  // weight/P layout [O][C][K]
        float w  = weight[wi];
        float pos = P[wi] + (float)PADV;
        pos = fminf(fmaxf(pos, 0.0f), 55.0f);
        float lof = floorf(pos);
        float fr  = pos - lof;                 // frac; lo=55 => fr=0 => wh=0
        m.x = w * (1.0f - fr);
        m.y = w * fr;
        m.z = __int_as_float((int)lof);        // 0..55
    }
    g_meta[n] = m;
}

__global__ __launch_bounds__(256) void conv_kernel(
    const float* __restrict__ x,
    const float* __restrict__ bias,
    float* __restrict__ out) {

    __shared__ float  sx[C_CHUNK][WIN];
    __shared__ float4 smeta[C_CHUNK][O_TILE][8];

    const int tid = threadIdx.x;
    const int w   = tid >> 5;      // warp 0..7
    const int l   = tid & 31;      // lane = t offset
    const int tb  = blockIdx.x * T_TILE;
    const int ob  = blockIdx.y * O_TILE;
    const int b   = blockIdx.z;

    float acc[4][4];
    #pragma unroll
    for (int oi = 0; oi < 4; ++oi) {
        float bv = bias[ob + 4 * w + oi];
        #pragma unroll
        for (int j = 0; j < 4; ++j) acc[oi][j] = bv;
    }

    const float* xb = x + (size_t)b * CIN * LIN;

    for (int c0 = 0; c0 < CIN; c0 += C_CHUNK) {
        __syncthreads();

        // stage x windows: sx[r][col] = xpad[b, c0+r, tb + col], col in [0,184)
        #pragma unroll
        for (int i = tid; i < C_CHUNK * WIN; i += 256) {
            int r   = i / WIN;
            int col = i - r * WIN;
            int src = tb - PADV + col;
            float v = 0.0f;
            if (src >= 0 && src < LIN) v = xb[(size_t)(c0 + r) * LIN + src];
            sx[r][col] = v;
        }

        // stage tap metadata for (c-chunk, o-tile): 2048 float4, coalesced
        const float4* gm = g_meta + ((size_t)c0 * COUT + ob) * 8;
        #pragma unroll
        for (int i = tid; i < C_CHUNK * O_TILE * 8; i += 256) {
            int c   = i >> 8;        // 32 o * 8 k = 256 per c
            int rem = i & 255;
            ((float4*)smeta)[i] = gm[(size_t)c * (COUT * 8) + rem];
        }
        __syncthreads();

        #pragma unroll
        for (int oi = 0; oi < 4; ++oi) {
            const int ol = 4 * w + oi;
            #pragma unroll 2
            for (int c = 0; c < C_CHUNK; ++c) {
                #pragma unroll
                for (int k = 0; k < KTAPS; ++k) {
                    float4 m = smeta[c][ol][k];       // broadcast LDS.128
                    int lo = __float_as_int(m.z);
                    const float* p = &sx[c][lo + l];  // conflict-free, lanes consecutive
                    #pragma unroll
                    for (int j = 0; j < 4; ++j) {
                        acc[oi][j] = fmaf(m.x, p[32 * j],     acc[oi][j]);
                        acc[oi][j] = fmaf(m.y, p[32 * j + 1], acc[oi][j]);
                    }
                }
            }
        }
    }

    #pragma unroll
    for (int oi = 0; oi < 4; ++oi) {
        float* op = out + ((size_t)b * COUT + ob + 4 * w + oi) * LOUT + tb;
        #pragma unroll
        for (int j = 0; j < 4; ++j) {
            int t = 32 * j + l;
            if (tb + t < LOUT) op[t] = acc[oi][j];
        }
    }
}

extern "C" void kernel_launch(void* const* d_in, const int* in_sizes, int n_in,
                              void* d_out, int out_size) {
    const float* x      = (const float*)d_in[0];  // [32,256,4096]
    const float* weight = (const float*)d_in[1];  // [256,256,7]
    const float* P      = (const float*)d_in[2];  // [256,256,7]
    const float* bias   = (const float*)d_in[3];  // [256]
    float* out          = (float*)d_out;          // [32,256,4097]

    prep_kernel<<<(CIN * COUT * 8 + 255) / 256, 256>>>(weight, P);

    dim3 grid((LOUT + T_TILE - 1) / T_TILE, COUT / O_TILE, BATCH);
    conv_kernel<<<grid, 256>>>(x, bias, out);
}

// round 3
// speedup vs baseline: 1.4529x; 1.4529x over previous
#include <cuda_runtime.h>

// Dcls1d (learnable-spacing dilated conv1d), batch-in-lanes formulation.
//
// out[b,o,t] = bias[o] + sum_{c,k} wl[o,c,k]*xpad[b,c,t+lo] + wh[o,c,k]*xpad[b,c,t+lo+1]
//   lo = floor(clip(P[o,c,k]+28, 0, 55)), wl = w*(1-frac), wh = w*frac.
//
// Layout: lane = batch (B=32 == warpSize), warp = one output channel o,
// block = 8 warps x one 32-wide t-tile. x windows for CCH=4 input channels
// are staged in smem as sx[ci][b][col] (col pad 89, odd -> conflict-free
// column-broadcast LDS.32). Per tap, the 33-value t-window is loaded once
// and reused by both lerp sub-taps across all 32 t's:
//     acc[t] += wl*v[t] + wh*v[t+1]
// -> 33 crossbar phases per 2048 lane-FMAs (2.4x fewer smem bytes than R1).
// Tap metadata {wl, wh, lo} is warp-uniform and read via __ldg (L1-cached,
// stays off the smem crossbar), prefetched one tap ahead.

#define CIN   256
#define COUT  256
#define KT    7
#define LIN   4096
#define LOUT  4097       // 4096 + 2*28 - 56 + 1
#define PADV  28

#define TT    32         // t-tile per block (per-lane acc registers)
#define WPAD  89         // 32 + 56 + 1, odd -> conflict-free smem rows
#define CCH   4          // input channels staged per __syncthreads pair
#define NW    8          // warps per block, each owns one o

// Tap table [o][c][k] as float4 {wl, wh, bits(lo), 0}: 256*256*7*16 B = 7.3 MB
__device__ float4 g_meta[(size_t)COUT * CIN * KT];

__global__ void prep_kernel(const float* __restrict__ weight,
                            const float* __restrict__ P) {
    int n = blockIdx.x * blockDim.x + threadIdx.x;
    if (n >= COUT * CIN * KT) return;
    // weight/P are [O][C][K] row-major -> same linear index as g_meta
    float w   = weight[n];
    float pos = P[n] + (float)PADV;
    pos = fminf(fmaxf(pos, 0.0f), 55.0f);
    float lof = floorf(pos);
    float fr  = pos - lof;               // lo==55 -> fr==0 -> wh==0 (matches ref clamp)
    float4 m;
    m.x = w * (1.0f - fr);
    m.y = w * fr;
    m.z = __int_as_float((int)lof);      // 0..55
    m.w = 0.0f;
    g_meta[n] = m;
}

__global__ __launch_bounds__(256) void conv_kernel(
    const float* __restrict__ x,
    const float* __restrict__ bias,
    float* __restrict__ out) {

    __shared__ float sx[CCH][32][WPAD];  // 45.6 KB

    const int tid = threadIdx.x;
    const int w   = tid >> 5;            // warp -> output channel within tile
    const int l   = tid & 31;            // lane -> batch index
    const int tb  = blockIdx.x * TT;
    const int o   = blockIdx.y * NW + w;

    float acc[TT];
    {
        const float bv = bias[o];
        #pragma unroll
        for (int t = 0; t < TT; ++t) acc[t] = bv;
    }

    for (int c0 = 0; c0 < CIN; c0 += CCH) {
        __syncthreads();
        // stage CCH channel windows: sx[ci][b][col] = xpad[b, c0+ci, tb-28+col]
        for (int i = tid; i < CCH * 32 * WPAD; i += 256) {
            int ci  = i / (32 * WPAD);
            int r   = i - ci * (32 * WPAD);
            int b   = r / WPAD;
            int col = r - b * WPAD;
            int src = tb - PADV + col;
            float v = 0.0f;
            if (src >= 0 && src < LIN)
                v = x[((size_t)b * CIN + (c0 + ci)) * LIN + src];
            sx[ci][b][col] = v;
        }
        __syncthreads();

        #pragma unroll 1
        for (int ci = 0; ci < CCH; ++ci) {
            const float*  row = &sx[ci][l][0];
            const float4* mt  = g_meta + ((size_t)o * CIN + (c0 + ci)) * KT;
            float4 mc = __ldg(&mt[0]);
            #pragma unroll 1
            for (int k = 0; k < KT; ++k) {
                float4 mn = __ldg(&mt[(k < KT - 1) ? k + 1 : k]);  // prefetch next tap
                const int lo = __float_as_int(mc.z);               // warp-uniform
                const float* p = row + lo;
                float vp = p[0];                                    // conflict-free LDS.32
                #pragma unroll
                for (int t = 0; t < TT; ++t) {
                    float vc = p[t + 1];
                    acc[t] = fmaf(mc.x, vp, fmaf(mc.y, vc, acc[t]));
                    vp = vc;
                }
                mc = mn;
            }
        }
    }

    // per-lane contiguous 128 B run; L2 merges sectors across the 32 STG.32
    float* op = out + ((size_t)l * COUT + o) * LOUT + tb;
    #pragma unroll
    for (int t = 0; t < TT; ++t)
        if (tb + t < LOUT) op[t] = acc[t];
}

extern "C" void kernel_launch(void* const* d_in, const int* in_sizes, int n_in,
                              void* d_out, int out_size) {
    const float* x      = (const float*)d_in[0];  // [32,256,4096]
    const float* weight = (const float*)d_in[1];  // [256,256,7]
    const float* P      = (const float*)d_in[2];  // [256,256,7]
    const float* bias   = (const float*)d_in[3];  // [256]
    float* out          = (float*)d_out;          // [32,256,4097]

    prep_kernel<<<(COUT * CIN * KT + 255) / 256, 256>>>(weight, P);

    dim3 grid((LOUT + TT - 1) / TT, COUT / NW);   // (129, 32)
    conv_kernel<<<grid, 256>>>(x, bias, out);
}

// round 7
// speedup vs baseline: 1.5292x; 1.0525x over previous
#include <cuda_runtime.h>

// Dcls1d (learnable-spacing dilated conv1d), batch-in-lanes formulation.
//
// out[b,o,t] = bias[o] + sum_{c,k} wl[o,c,k]*xpad[b,c,t+lo] + wh[o,c,k]*xpad[b,c,t+lo+1]
//   lo = floor(clip(P[o,c,k]+28, 0, 55)), wl = w*(1-frac), wh = w*frac.
//
// Layout: lane = batch (B=32 == warpSize), warp = one output channel o,
// block = 8 warps x one 32-wide t-tile. x windows for CCH=4 input channels
// are staged in smem as sx[ci][b][col] (col pad 89, odd -> conflict-free
// column-broadcast LDS.32). Per tap, the 33-value t-window is loaded once
// and reused by both lerp sub-taps across all 32 t's:
//     acc[t] += wl*v[t] + wh*v[t+1]
// -> 33 crossbar phases per 2048 lane-FMAs (2.4x fewer smem bytes than R1).
// Tap metadata {wl, wh, lo} is warp-uniform and read via __ldg (L1-cached,
// stays off the smem crossbar), prefetched one tap ahead.

#define CIN   256
#define COUT  256
#define KT    7
#define LIN   4096
#define LOUT  4097       // 4096 + 2*28 - 56 + 1
#define PADV  28

#define TT    32         // t-tile per block (per-lane acc registers)
#define WPAD  89         // 32 + 56 + 1, odd -> conflict-free smem rows
#define CCH   4          // input channels staged per __syncthreads pair
#define NW    8          // warps per block, each owns one o

// Tap table [o][c][k] as float4 {wl, wh, bits(lo), 0}: 256*256*7*16 B = 7.3 MB
__device__ float4 g_meta[(size_t)COUT * CIN * KT];

__global__ void prep_kernel(const float* __restrict__ weight,
                            const float* __restrict__ P) {
    int n = blockIdx.x * blockDim.x + threadIdx.x;
    if (n >= COUT * CIN * KT) return;
    // weight/P are [O][C][K] row-major -> same linear index as g_meta
    float w   = weight[n];
    float pos = P[n] + (float)PADV;
    pos = fminf(fmaxf(pos, 0.0f), 55.0f);
    float lof = floorf(pos);
    float fr  = pos - lof;               // lo==55 -> fr==0 -> wh==0 (matches ref clamp)
    float4 m;
    m.x = w * (1.0f - fr);
    m.y = w * fr;
    m.z = __int_as_float((int)lof);      // 0..55
    m.w = 0.0f;
    g_meta[n] = m;
}

__global__ __launch_bounds__(256) void conv_kernel(
    const float* __restrict__ x,
    const float* __restrict__ bias,
    float* __restrict__ out) {

    __shared__ float sx[CCH][32][WPAD];  // 45.6 KB

    const int tid = threadIdx.x;
    const int w   = tid >> 5;            // warp -> output channel within tile
    const int l   = tid & 31;            // lane -> batch index
    const int tb  = blockIdx.x * TT;
    const int o   = blockIdx.y * NW + w;

    float acc[TT];
    {
        const float bv = bias[o];
        #pragma unroll
        for (int t = 0; t < TT; ++t) acc[t] = bv;
    }

    for (int c0 = 0; c0 < CIN; c0 += CCH) {
        __syncthreads();
        // stage CCH channel windows: sx[ci][b][col] = xpad[b, c0+ci, tb-28+col]
        for (int i = tid; i < CCH * 32 * WPAD; i += 256) {
            int ci  = i / (32 * WPAD);
            int r   = i - ci * (32 * WPAD);
            int b   = r / WPAD;
            int col = r - b * WPAD;
            int src = tb - PADV + col;
            float v = 0.0f;
            if (src >= 0 && src < LIN)
                v = x[((size_t)b * CIN + (c0 + ci)) * LIN + src];
            sx[ci][b][col] = v;
        }
        __syncthreads();

        #pragma unroll 1
        for (int ci = 0; ci < CCH; ++ci) {
            const float*  row = &sx[ci][l][0];
            const float4* mt  = g_meta + ((size_t)o * CIN + (c0 + ci)) * KT;
            float4 mc = __ldg(&mt[0]);
            #pragma unroll 1
            for (int k = 0; k < KT; ++k) {
                float4 mn = __ldg(&mt[(k < KT - 1) ? k + 1 : k]);  // prefetch next tap
                const int lo = __float_as_int(mc.z);               // warp-uniform
                const float* p = row + lo;
                float vp = p[0];                                    // conflict-free LDS.32
                #pragma unroll
                for (int t = 0; t < TT; ++t) {
                    float vc = p[t + 1];
                    acc[t] = fmaf(mc.x, vp, fmaf(mc.y, vc, acc[t]));
                    vp = vc;
                }
                mc = mn;
            }
        }
    }

    // per-lane contiguous 128 B run; L2 merges sectors across the 32 STG.32
    float* op = out + ((size_t)l * COUT + o) * LOUT + tb;
    #pragma unroll
    for (int t = 0; t < TT; ++t)
        if (tb + t < LOUT) op[t] = acc[t];
}

extern "C" void kernel_launch(void* const* d_in, const int* in_sizes, int n_in,
                              void* d_out, int out_size) {
    const float* x      = (const float*)d_in[0];  // [32,256,4096]
    const float* weight = (const float*)d_in[1];  // [256,256,7]
    const float* P      = (const float*)d_in[2];  // [256,256,7]
    const float* bias   = (const float*)d_in[3];  // [256]
    float* out          = (float*)d_out;          // [32,256,4097]

    prep_kernel<<<(COUT * CIN * KT + 255) / 256, 256>>>(weight, P);

    dim3 grid((LOUT + TT - 1) / TT, COUT / NW);   // (129, 32)
    conv_kernel<<<grid, 256>>>(x, bias, out);
}

// round 10
// speedup vs baseline: 2.4583x; 1.6076x over previous
#include <cuda_runtime.h>
#include <cstdint>

// Dcls1d as implicit GEMM on mma.sync.m16n8k8 tf32 (family-target safe; the
// harness builds this TU as compute_103 so tcgen05/TMEM are unavailable).
//
// Dense view: out[b,o,t] = bias[o] + sum_{c,d<56} dk[o][c][d]*xpad[b][c][t+d]
// GEMM: M=256(o) x N=32*4097(b,t) x K=256*64(c,d).
//   A[m=o][k=(c,dl)] = dk[o][c][dl]        (prep kernel, tf32-rounded, 16MB)
//   B[n=t][k=(c,dl)] = xpad[b][c][tb+t+dl] (Hankel: read from a 320-float
//                                           smem window, broadcast LDS)
// CTA: 128(M) x 256(N), one b. 16 warps = 2(M) x 8(N), warp tile 64x32 ->
// 16 m16n8k8 MMAs per k-step, 8 k-steps per c-chunk (k=64).
// A chunk (128x64, rows padded to 68 floats -> fragment LDS hit all 32 banks)
// is register-double-buffered: LDG next chunk while computing current.
//
// R10 fix: epilogue stores are SCALAR. Output rows have length 4097 (odd), so
// row bases are only 4-byte aligned and float2 stores fault (R9 failure).

#define CIN   256
#define COUT  256
#define KT    7
#define LIN   4096
#define LOUT  4097
#define PADV  28
#define KC    64            // k per c-chunk
#define MTILE 128           // CTA M
#define NTILE 256           // CTA N
#define APAD  68            // floats per padded A smem row
#define XWIN  320           // t+dl window: 256 + 63 + 1
#define NTHR  512

// [mtile(2)][c(256)][m(128)][dl(64)] tf32 floats = 16 MB
__device__ __align__(16) float g_A[(size_t)2 * CIN * MTILE * KC];

__device__ __forceinline__ uint32_t f2tf32(float f) {
    uint32_t u;
    asm("cvt.rna.tf32.f32 %0, %1;" : "=r"(u) : "f"(f));
    return u;
}

// ---------------- prep: dense lerped kernel, tf32-rounded -------------------
__global__ void prep_kernel(const float* __restrict__ weight,
                            const float* __restrict__ P) {
    int n = blockIdx.x * blockDim.x + threadIdx.x;   // one thread per (o,c)
    if (n >= COUT * CIN) return;
    int o = n >> 8, c = n & 255;
    float dk[KC];
    #pragma unroll
    for (int i = 0; i < KC; ++i) dk[i] = 0.0f;
    #pragma unroll
    for (int k = 0; k < KT; ++k) {
        size_t idx = ((size_t)o * CIN + c) * KT + k;
        float w   = weight[idx];
        float pos = P[idx] + (float)PADV;
        pos = fminf(fmaxf(pos, 0.0f), 55.0f);
        float lof = floorf(pos);
        float fr  = pos - lof;
        int lo = (int)lof;                    // 0..55
        dk[lo]     += w * (1.0f - fr);
        dk[lo + 1] += w * fr;                 // lo==55 -> fr==0
    }
    int mt = o >> 7, m = o & 127;
    float* dst = g_A + ((size_t)(mt * CIN + c) * MTILE + m) * KC;
    #pragma unroll
    for (int i = 0; i < KC; ++i) dst[i] = __uint_as_float(f2tf32(dk[i]));
}

// ---------------- main GEMM -------------------------------------------------
__global__ void __launch_bounds__(NTHR, 1) conv_kernel(
    const float* __restrict__ x,
    const float* __restrict__ bias,
    float* __restrict__ out) {

    __shared__ float sA[MTILE * APAD];   // 34.8 KB
    __shared__ float sX[XWIN];

    const int tid   = threadIdx.x;
    const int wid   = tid >> 5, lane = tid & 31;
    const int warpM = wid >> 3, warpN = wid & 7;
    const int g     = lane >> 2, tg = lane & 3;
    const int tb    = blockIdx.x * NTILE;
    const int mb    = blockIdx.y;
    const int b     = blockIdx.z;

    float acc[4][4][4];                  // [mt][nt][reg]
    #pragma unroll
    for (int i = 0; i < 4; ++i)
        #pragma unroll
        for (int j = 0; j < 4; ++j)
            #pragma unroll
            for (int r = 0; r < 4; ++r) acc[i][j][r] = 0.0f;

    const float* gA = g_A + (size_t)mb * CIN * MTILE * KC;
    const float* xb = x + (size_t)b * CIN * LIN;

    // register prefetch: A (16 floats) + one xwin value per thread
    float4 pa[4];
    float  px = 0.0f;
    {
        const float4* src = reinterpret_cast<const float4*>(gA) + (size_t)tid * 4;
        #pragma unroll
        for (int j = 0; j < 4; ++j) pa[j] = src[j];
        int s = tb - PADV + tid;
        if (tid < XWIN)
            px = (s >= 0 && s < LIN) ? __uint_as_float(f2tf32(xb[s])) : 0.0f;
    }

    const int rowQ = tid >> 2;                    // A stage row (16 floats/thread)
    const int kQ   = (tid & 3) * 16;

    for (int c = 0; c < CIN; ++c) {
        // store prefetched chunk to smem
        float* d = sA + rowQ * APAD + kQ;
        #pragma unroll
        for (int j = 0; j < 4; ++j)
            reinterpret_cast<float4*>(d)[j] = pa[j];
        if (tid < XWIN) sX[tid] = px;
        __syncthreads();

        // issue prefetch for next chunk (completes under compute)
        if (c + 1 < CIN) {
            const float4* src = reinterpret_cast<const float4*>(
                gA + (size_t)(c + 1) * MTILE * KC) + (size_t)tid * 4;
            #pragma unroll
            for (int j = 0; j < 4; ++j) pa[j] = src[j];
            int s = tb - PADV + tid;
            if (tid < XWIN)
                px = (s >= 0 && s < LIN)
                   ? __uint_as_float(f2tf32(xb[(size_t)(c + 1) * LIN + s])) : 0.0f;
        }

        // compute: 8 k-steps of m16n8k8
        const float* aBase = sA + (warpM * 64 + g) * APAD;
        const int    nBase = warpN * 32 + g;
        #pragma unroll
        for (int ks = 0; ks < 8; ++ks) {
            const int k0 = ks * 8 + tg;
            uint32_t a[4][4];
            #pragma unroll
            for (int mt = 0; mt < 4; ++mt) {
                const float* ap = aBase + mt * 16 * APAD + k0;
                a[mt][0] = __float_as_uint(ap[0]);
                a[mt][1] = __float_as_uint(ap[8 * APAD]);
                a[mt][2] = __float_as_uint(ap[4]);
                a[mt][3] = __float_as_uint(ap[8 * APAD + 4]);
            }
            #pragma unroll
            for (int nt = 0; nt < 4; ++nt) {
                const int xi = nBase + nt * 8 + k0;      // broadcast LDS
                uint32_t b0 = __float_as_uint(sX[xi]);
                uint32_t b1 = __float_as_uint(sX[xi + 4]);
                #pragma unroll
                for (int mt = 0; mt < 4; ++mt) {
                    asm volatile(
                        "mma.sync.aligned.m16n8k8.row.col.f32.tf32.tf32.f32 "
                        "{%0,%1,%2,%3}, {%4,%5,%6,%7}, {%8,%9}, {%0,%1,%2,%3};"
                        : "+f"(acc[mt][nt][0]), "+f"(acc[mt][nt][1]),
                          "+f"(acc[mt][nt][2]), "+f"(acc[mt][nt][3])
                        : "r"(a[mt][0]), "r"(a[mt][1]), "r"(a[mt][2]), "r"(a[mt][3]),
                          "r"(b0), "r"(b1));
                }
            }
        }
        __syncthreads();
    }

    // epilogue: c0,c1 -> (o, t..t+1), c2,c3 -> (o+8, t..t+1). SCALAR stores:
    // LOUT=4097 is odd, so row bases are 4B-aligned only (float2 would fault).
    #pragma unroll
    for (int mt = 0; mt < 4; ++mt) {
        const int o  = mb * MTILE + warpM * 64 + mt * 16 + g;
        const float bv0 = bias[o];
        const float bv8 = bias[o + 8];
        float* r0 = out + ((size_t)b * COUT + o) * LOUT;
        float* r8 = r0 + 8 * LOUT;
        #pragma unroll
        for (int nt = 0; nt < 4; ++nt) {
            const int t = tb + warpN * 32 + nt * 8 + tg * 2;
            if (t < LOUT) {
                r0[t] = acc[mt][nt][0] + bv0;
                r8[t] = acc[mt][nt][2] + bv8;
            }
            if (t + 1 < LOUT) {
                r0[t + 1] = acc[mt][nt][1] + bv0;
                r8[t + 1] = acc[mt][nt][3] + bv8;
            }
        }
    }
}

extern "C" void kernel_launch(void* const* d_in, const int* in_sizes, int n_in,
                              void* d_out, int out_size) {
    const float* x      = (const float*)d_in[0];  // [32,256,4096]
    const float* weight = (const float*)d_in[1];  // [256,256,7]
    const float* P      = (const float*)d_in[2];  // [256,256,7]
    const float* bias   = (const float*)d_in[3];  // [256]
    float* out          = (float*)d_out;          // [32,256,4097]

    prep_kernel<<<(COUT * CIN + 255) / 256, 256>>>(weight, P);

    dim3 grid((LOUT + NTILE - 1) / NTILE, 2, 32);  // (17, 2, 32) = 1088 CTAs
    conv_kernel<<<grid, NTHR>>>(x, bias, out);
}

// round 11
// speedup vs baseline: 3.5173x; 1.4308x over previous
#include <cuda_runtime.h>
#include <cstdint>

// Dcls1d as implicit GEMM on mma.sync.m16n8k8 tf32 (family-target compute_103:
// tcgen05/TMEM unavailable; cp.async (sm_80+) is).
//
// Dense view: out[b,o,t] = bias[o] + sum_{c,d<56} dk[o][c][d]*xpad[b][c][t+d]
// (reference clamps hi=min(lo+1,55) and pos<=55 -> frac(lo=55)=0, so the dense
//  kernel is exactly 56 wide: 7 k-steps of 8, not 8).
// GEMM: M=256(o) x N=32*4097(b,t) x K=256*56(c,d).
// CTA: 128(M) x 256(N), one b. 16 warps = 2(M) x 8(N), warp tile 64x32.
//
// A is prebuilt in MMA-FRAGMENT ORDER: g_Af[mt][c][B(8)][ks(7)][lane(32)][4]
// so each m16-block fragment is one LDS.128 per lane. B is Hankel: read as
// broadcast LDS.32 from a 320-float x-window. Both staged via cp.async with
// 2-stage double buffering and a single __syncthreads per c-chunk.

#define CIN   256
#define COUT  256
#define KT    7
#define LIN   4096
#define LOUT  4097
#define PADV  28
#define KS_N  7              // k-steps per c-chunk (K=56)
#define MTILE 128
#define NTILE 256
#define XWIN  320
#define NTHR  512

#define AFCH     (8 * KS_N * 128)     // floats per (mt, c) A chunk = 7168
#define AFBYTES  (AFCH * 4)           // 28672
#define XBYTES   (XWIN * 4)           // 1280
#define SM_X0    (2 * AFBYTES)        // smem carve: [A0][A1][X0][X1]
#define SMEM_TOTAL (2 * AFBYTES + 2 * XBYTES)   // 59904

// [mt(2)][c(256)][B(8)][ks(7)][lane(32)][slot(4)] = 14.7 MB
__device__ __align__(16) float g_Af[(size_t)2 * CIN * AFCH];

__device__ __forceinline__ uint32_t f2tf32(float f) {
    uint32_t u;
    asm("cvt.rna.tf32.f32 %0, %1;" : "=r"(u) : "f"(f));
    return u;
}
__device__ __forceinline__ uint32_t smem_u32(const void* p) {
    uint32_t a;
    asm("{ .reg .u64 t; cvta.to.shared.u64 t, %1; cvt.u32.u64 %0, t; }" : "=r"(a) : "l"(p));
    return a;
}
__device__ __forceinline__ void cp16(uint32_t dst, const void* src) {
    asm volatile("cp.async.cg.shared.global [%0], [%1], 16;" :: "r"(dst), "l"(src));
}

// ---------------- prep: dense lerped kernel -> fragment-ordered A -----------
__global__ void prep_kernel(const float* __restrict__ weight,
                            const float* __restrict__ P) {
    int n = blockIdx.x * blockDim.x + threadIdx.x;   // one thread per (o,c)
    if (n >= COUT * CIN) return;
    int o = n >> 8, c = n & 255;
    float dk[57];
    #pragma unroll
    for (int i = 0; i < 57; ++i) dk[i] = 0.0f;
    #pragma unroll
    for (int k = 0; k < KT; ++k) {
        size_t idx = ((size_t)o * CIN + c) * KT + k;
        float w   = weight[idx];
        float pos = P[idx] + (float)PADV;
        pos = fminf(fmaxf(pos, 0.0f), 55.0f);
        float lof = floorf(pos);
        float fr  = pos - lof;
        int lo = (int)lof;                    // 0..55; lo==55 -> fr==0
        dk[lo]     += w * (1.0f - fr);
        dk[lo + 1] += w * fr;                 // dk[56] only ever += 0
    }
    const int mt = o >> 7, m = o & 127;
    const int B = m >> 4, r = m & 15;
    const int g = r & 7, hi = r >> 3;         // hi=0 -> slots 0/2, hi=1 -> 1/3
    float* base = g_Af + (((size_t)mt * CIN + c) * 8 + B) * (KS_N * 128);
    #pragma unroll
    for (int ks = 0; ks < KS_N; ++ks)
        #pragma unroll
        for (int tg = 0; tg < 4; ++tg) {
            const int lane = g * 4 + tg;
            base[ks * 128 + lane * 4 + hi]     = __uint_as_float(f2tf32(dk[ks * 8 + tg]));
            base[ks * 128 + lane * 4 + hi + 2] = __uint_as_float(f2tf32(dk[ks * 8 + tg + 4]));
        }
}

// ---------------- main GEMM -------------------------------------------------
__global__ void __launch_bounds__(NTHR, 1) conv_kernel(
    const float* __restrict__ x,
    const float* __restrict__ bias,
    float* __restrict__ out) {

    extern __shared__ __align__(16) char smem[];

    const int tid   = threadIdx.x;
    const int wid   = tid >> 5, lane = tid & 31;
    const int warpM = wid >> 3, warpN = wid & 7;
    const int g     = lane >> 2, tg = lane & 3;
    const int tb    = blockIdx.x * NTILE;
    const int mb    = blockIdx.y;
    const int b     = blockIdx.z;

    const float* gA = g_Af + (size_t)mb * CIN * AFCH;
    const float* xb = x + (size_t)b * CIN * LIN;

    // x-window valid range for this CTA (multiples of 4; s0 = tb-28 ≡ 0 mod 4)
    const int s0 = tb - PADV;
    const int f0 = (s0 < 0) ? -s0 : 0;                       // 0 or 28
    const int f1 = (LIN - s0 < XWIN) ? (LIN - s0) : XWIN;    // 320 or 28
    const int q0 = f0 >> 2, q1 = f1 >> 2;

    const uint32_t sb = smem_u32(smem);

    // pre-zero x-window boundary regions in both buffers (persist across chunks)
    for (int i = tid; i < 2 * XWIN; i += NTHR) {
        int bf = i / XWIN, j = i - bf * XWIN;
        if (j < f0 || j >= f1)
            reinterpret_cast<float*>(smem + SM_X0 + bf * XBYTES)[j] = 0.0f;
    }

    // stage chunk c into buffer bf (cp.async, no waits here)
    auto stage = [&](int c, int bf) {
        const float4* srcA = reinterpret_cast<const float4*>(gA + (size_t)c * AFCH);
        const uint32_t dA  = sb + bf * AFBYTES;
        #pragma unroll
        for (int q = tid; q < AFCH / 4; q += NTHR)
            cp16(dA + q * 16, srcA + q);
        if (tid < q1 - q0)
            cp16(sb + SM_X0 + bf * XBYTES + (q0 + tid) * 16,
                 xb + (size_t)c * LIN + s0 + (q0 + tid) * 4);
    };

    float acc[4][4][4];
    #pragma unroll
    for (int i = 0; i < 4; ++i)
        #pragma unroll
        for (int j = 0; j < 4; ++j)
            #pragma unroll
            for (int r = 0; r < 4; ++r) acc[i][j][r] = 0.0f;

    stage(0, 0);
    asm volatile("cp.async.commit_group;" ::: "memory");

    for (int c = 0; c < CIN; ++c) {
        const int buf = c & 1;
        asm volatile("cp.async.wait_group 0;" ::: "memory");
        __syncthreads();
        if (c + 1 < CIN) {
            stage(c + 1, buf ^ 1);
            asm volatile("cp.async.commit_group;" ::: "memory");
        }

        const float* aw = reinterpret_cast<const float*>(smem + buf * AFBYTES)
                        + (warpM * 4) * (KS_N * 128);
        const float* xw = reinterpret_cast<const float*>(smem + SM_X0 + buf * XBYTES);

        #pragma unroll
        for (int ks = 0; ks < KS_N; ++ks) {
            uint32_t a[4][4];
            #pragma unroll
            for (int mt = 0; mt < 4; ++mt) {
                float4 f = reinterpret_cast<const float4*>(
                               aw + (mt * KS_N + ks) * 128)[lane];   // LDS.128
                a[mt][0] = __float_as_uint(f.x);
                a[mt][1] = __float_as_uint(f.y);
                a[mt][2] = __float_as_uint(f.z);
                a[mt][3] = __float_as_uint(f.w);
            }
            const int xbase = warpN * 32 + g + ks * 8 + tg;
            #pragma unroll
            for (int nt = 0; nt < 4; ++nt) {
                uint32_t b0 = __float_as_uint(xw[xbase + nt * 8]);
                uint32_t b1 = __float_as_uint(xw[xbase + nt * 8 + 4]);
                #pragma unroll
                for (int mt = 0; mt < 4; ++mt) {
                    asm volatile(
                        "mma.sync.aligned.m16n8k8.row.col.f32.tf32.tf32.f32 "
                        "{%0,%1,%2,%3}, {%4,%5,%6,%7}, {%8,%9}, {%0,%1,%2,%3};"
                        : "+f"(acc[mt][nt][0]), "+f"(acc[mt][nt][1]),
                          "+f"(acc[mt][nt][2]), "+f"(acc[mt][nt][3])
                        : "r"(a[mt][0]), "r"(a[mt][1]), "r"(a[mt][2]), "r"(a[mt][3]),
                          "r"(b0), "r"(b1));
                }
            }
        }
        __syncthreads();   // protect buf reuse: next-next stage writes this buf
    }

    // epilogue: scalar stores (LOUT=4097 odd -> rows only 4B-aligned)
    #pragma unroll
    for (int mt = 0; mt < 4; ++mt) {
        const int o  = mb * MTILE + warpM * 64 + mt * 16 + g;
        const float bv0 = bias[o];
        const float bv8 = bias[o + 8];
        float* r0 = out + ((size_t)b * COUT + o) * LOUT;
        float* r8 = r0 + 8 * LOUT;
        #pragma unroll
        for (int nt = 0; nt < 4; ++nt) {
            const int t = tb + warpN * 32 + nt * 8 + tg * 2;
            if (t < LOUT) {
                r0[t] = acc[mt][nt][0] + bv0;
                r8[t] = acc[mt][nt][2] + bv8;
            }
            if (t + 1 < LOUT) {
                r0[t + 1] = acc[mt][nt][1] + bv0;
                r8[t + 1] = acc[mt][nt][3] + bv8;
            }
        }
    }
}

extern "C" void kernel_launch(void* const* d_in, const int* in_sizes, int n_in,
                              void* d_out, int out_size) {
    const float* x      = (const float*)d_in[0];  // [32,256,4096]
    const float* weight = (const float*)d_in[1];  // [256,256,7]
    const float* P      = (const float*)d_in[2];  // [256,256,7]
    const float* bias   = (const float*)d_in[3];  // [256]
    float* out          = (float*)d_out;          // [32,256,4097]

    cudaFuncSetAttribute(conv_kernel, cudaFuncAttributeMaxDynamicSharedMemorySize,
                         SMEM_TOTAL);

    prep_kernel<<<(COUT * CIN + 255) / 256, 256>>>(weight, P);

    dim3 grid((LOUT + NTILE - 1) / NTILE, 2, 32);  // (17, 2, 32) = 1088 CTAs
    conv_kernel<<<grid, NTHR, SMEM_TOTAL>>>(x, bias, out);
}

// round 13
// speedup vs baseline: 3.6758x; 1.0451x over previous
#include <cuda_runtime.h>
#include <cstdint>

// Dcls1d as implicit GEMM on mma.sync.m16n8k8 tf32 (family-target compute_103).
//
// out[b,o,t] = bias[o] + sum_{c,d<56} dk[o][c][d]*xpad[b][c][t+d]
// GEMM: M=256(o) x N=32*4096(b,t) x K=256*56(c,d); the single t=4096 column
// is handled by a tiny tail kernel (only d<28 taps reach valid input there).
//
// CTA: 128(M) x 256(N), one b. 16 warps = 2(M) x 8(N), warp tile 64x32.
// A prebuilt in MMA-fragment order (one LDS.128 per m16 fragment); B is
// Hankel: broadcast LDS.32 from a 320-float x-window.
// 3-stage cp.async pipeline, wait_group 1, ONE __syncthreads per chunk.

#define CIN   256
#define COUT  256
#define KT    7
#define LIN   4096
#define LOUT  4097
#define PADV  28
#define KS_N  7
#define MTILE 128
#define NTILE 256
#define NTT   16             // N-tiles over t (covers 0..4095)
#define XWIN  320
#define NTHR  512

#define AFCH     (8 * KS_N * 128)     // floats per (mt,c) A chunk = 7168
#define AFBYTES  (AFCH * 4)           // 28672
#define XBYTES   (XWIN * 4)           // 1280
#define SM_X0    (3 * AFBYTES)
#define SMEM_TOTAL (3 * AFBYTES + 3 * XBYTES)   // 89856

// [mt(2)][c(256)][B(8)][ks(7)][lane(32)][slot(4)] = 14.7 MB
__device__ __align__(16) float g_Af[(size_t)2 * CIN * AFCH];

__device__ __forceinline__ uint32_t f2tf32(float f) {
    uint32_t u;
    asm("cvt.rna.tf32.f32 %0, %1;" : "=r"(u) : "f"(f));
    return u;
}
__device__ __forceinline__ uint32_t smem_u32(const void* p) {
    uint32_t a;
    asm("{ .reg .u64 t; cvta.to.shared.u64 t, %1; cvt.u32.u64 %0, t; }" : "=r"(a) : "l"(p));
    return a;
}
__device__ __forceinline__ void cp16(uint32_t dst, const void* src) {
    asm volatile("cp.async.cg.shared.global [%0], [%1], 16;" :: "r"(dst), "l"(src));
}

// ---------------- prep: dense lerped kernel -> fragment-ordered A -----------
__global__ void prep_kernel(const float* __restrict__ weight,
                            const float* __restrict__ P) {
    int n = blockIdx.x * blockDim.x + threadIdx.x;   // one thread per (o,c)
    if (n >= COUT * CIN) return;
    int o = n >> 8, c = n & 255;
    float dk[57];
    #pragma unroll
    for (int i = 0; i < 57; ++i) dk[i] = 0.0f;
    #pragma unroll
    for (int k = 0; k < KT; ++k) {
        size_t idx = ((size_t)o * CIN + c) * KT + k;
        float w   = weight[idx];
        float pos = P[idx] + (float)PADV;
        pos = fminf(fmaxf(pos, 0.0f), 55.0f);
        float lof = floorf(pos);
        float fr  = pos - lof;
        int lo = (int)lof;                    // 0..55; lo==55 -> fr==0
        dk[lo]     += w * (1.0f - fr);
        dk[lo + 1] += w * fr;
    }
    const int mt = o >> 7, m = o & 127;
    const int B = m >> 4, r = m & 15;
    const int g = r & 7, hi = r >> 3;
    float* base = g_Af + (((size_t)mt * CIN + c) * 8 + B) * (KS_N * 128);
    #pragma unroll
    for (int ks = 0; ks < KS_N; ++ks)
        #pragma unroll
        for (int tg = 0; tg < 4; ++tg) {
            const int lane = g * 4 + tg;
            base[ks * 128 + lane * 4 + hi]     = __uint_as_float(f2tf32(dk[ks * 8 + tg]));
            base[ks * 128 + lane * 4 + hi + 2] = __uint_as_float(f2tf32(dk[ks * 8 + tg + 4]));
        }
}

// ---------------- main GEMM (t in [0, 4096)) --------------------------------
__global__ void __launch_bounds__(NTHR, 1) conv_kernel(
    const float* __restrict__ x,
    const float* __restrict__ bias,
    float* __restrict__ out) {

    extern __shared__ __align__(16) char smem[];

    const int tid   = threadIdx.x;
    const int wid   = tid >> 5, lane = tid & 31;
    const int warpM = wid >> 3, warpN = wid & 7;
    const int g     = lane >> 2, tg = lane & 3;
    const int tb    = blockIdx.x * NTILE;
    const int mb    = blockIdx.y;
    const int b     = blockIdx.z;

    const float* gA = g_Af + (size_t)mb * CIN * AFCH;
    const float* xb = x + (size_t)b * CIN * LIN;

    // x-window valid range (multiples of 4: s0 = tb-28 ≡ 0 mod 4)
    const int s0 = tb - PADV;
    const int f0 = (s0 < 0) ? -s0 : 0;
    const int f1 = (LIN - s0 < XWIN) ? (LIN - s0) : XWIN;
    const int q0 = f0 >> 2, q1 = f1 >> 2;

    const uint32_t sb = smem_u32(smem);

    // pre-zero x-window boundary regions in all 3 buffers (persist)
    for (int i = tid; i < 3 * XWIN; i += NTHR) {
        int bf = i / XWIN, j = i - bf * XWIN;
        if (j < f0 || j >= f1)
            reinterpret_cast<float*>(smem + SM_X0 + bf * XBYTES)[j] = 0.0f;
    }

    auto stage = [&](int c, int bf) {
        const float4* srcA = reinterpret_cast<const float4*>(gA + (size_t)c * AFCH);
        const uint32_t dA  = sb + bf * AFBYTES;
        #pragma unroll
        for (int q = tid; q < AFCH / 4; q += NTHR)
            cp16(dA + q * 16, srcA + q);
        if (tid < q1 - q0)
            cp16(sb + SM_X0 + bf * XBYTES + (q0 + tid) * 16,
                 xb + (size_t)c * LIN + s0 + (q0 + tid) * 4);
    };

    float acc[4][4][4];
    #pragma unroll
    for (int i = 0; i < 4; ++i)
        #pragma unroll
        for (int j = 0; j < 4; ++j)
            #pragma unroll
            for (int r = 0; r < 4; ++r) acc[i][j][r] = 0.0f;

    stage(0, 0);
    asm volatile("cp.async.commit_group;" ::: "memory");
    stage(1, 1);
    asm volatile("cp.async.commit_group;" ::: "memory");

    int bf = 0;                 // bf = c % 3
    for (int c = 0; c < CIN; ++c) {
        if (c + 1 < CIN)
            asm volatile("cp.async.wait_group 1;" ::: "memory");
        else
            asm volatile("cp.async.wait_group 0;" ::: "memory");
        __syncthreads();        // all warps done with compute(c-1); chunk c ready

        if (c + 2 < CIN) {
            int nb = bf + 2; if (nb >= 3) nb -= 3;
            stage(c + 2, nb);
            asm volatile("cp.async.commit_group;" ::: "memory");
        }

        const float* aw = reinterpret_cast<const float*>(smem + bf * AFBYTES)
                        + (warpM * 4) * (KS_N * 128);
        const float* xw = reinterpret_cast<const float*>(smem + SM_X0 + bf * XBYTES);

        #pragma unroll
        for (int ks = 0; ks < KS_N; ++ks) {
            uint32_t a[4][4];
            #pragma unroll
            for (int mt = 0; mt < 4; ++mt) {
                float4 f = reinterpret_cast<const float4*>(
                               aw + (mt * KS_N + ks) * 128)[lane];   // LDS.128
                a[mt][0] = __float_as_uint(f.x);
                a[mt][1] = __float_as_uint(f.y);
                a[mt][2] = __float_as_uint(f.z);
                a[mt][3] = __float_as_uint(f.w);
            }
            const int xbase = warpN * 32 + g + ks * 8 + tg;
            #pragma unroll
            for (int nt = 0; nt < 4; ++nt) {
                uint32_t b0 = __float_as_uint(xw[xbase + nt * 8]);
                uint32_t b1 = __float_as_uint(xw[xbase + nt * 8 + 4]);
                #pragma unroll
                for (int mt = 0; mt < 4; ++mt) {
                    asm volatile(
                        "mma.sync.aligned.m16n8k8.row.col.f32.tf32.tf32.f32 "
                        "{%0,%1,%2,%3}, {%4,%5,%6,%7}, {%8,%9}, {%0,%1,%2,%3};"
                        : "+f"(acc[mt][nt][0]), "+f"(acc[mt][nt][1]),
                          "+f"(acc[mt][nt][2]), "+f"(acc[mt][nt][3])
                        : "r"(a[mt][0]), "r"(a[mt][1]), "r"(a[mt][2]), "r"(a[mt][3]),
                          "r"(b0), "r"(b1));
                }
            }
        }
        if (++bf == 3) bf = 0;
    }

    // epilogue: scalar stores (LOUT odd -> rows 4B-aligned); all t <= 4095
    #pragma unroll
    for (int mt = 0; mt < 4; ++mt) {
        const int o  = mb * MTILE + warpM * 64 + mt * 16 + g;
        const float bv0 = bias[o];
        const float bv8 = bias[o + 8];
        float* r0 = out + ((size_t)b * COUT + o) * LOUT;
        float* r8 = r0 + 8 * LOUT;
        #pragma unroll
        for (int nt = 0; nt < 4; ++nt) {
            const int t = tb + warpN * 32 + nt * 8 + tg * 2;
            r0[t]     = acc[mt][nt][0] + bv0;
            r0[t + 1] = acc[mt][nt][1] + bv0;
            r8[t]     = acc[mt][nt][2] + bv8;
            r8[t + 1] = acc[mt][nt][3] + bv8;
        }
    }
}

// ---------------- tail: the single t = 4096 column --------------------------
// out[b,o,4096] = bias[o] + sum_{c, d<28} dk[o][c][d] * x[b][c][4068+d]
// (4096 + d - 28 < 4096 requires d < 28). One warp per (b,o), lanes split c.
__global__ void __launch_bounds__(256) tail_kernel(
    const float* __restrict__ x,
    const float* __restrict__ bias,
    float* __restrict__ out) {

    const int wg   = blockIdx.x * 8 + (threadIdx.x >> 5);  // 0..8191
    const int lane = threadIdx.x & 31;
    const int b = wg >> 8, o = wg & 255;

    const int mt = o >> 7, m = o & 127;
    const int B = m >> 4, r = m & 15;
    const int g = r & 7, hi = r >> 3;

    float s = 0.0f;
    for (int c = lane; c < CIN; c += 32) {
        const float* base = g_Af + (((size_t)mt * CIN + c) * 8 + B) * (KS_N * 128);
        const float* xr   = x + ((size_t)b * CIN + c) * LIN + 4068;
        #pragma unroll
        for (int ks = 0; ks < 4; ++ks)
            #pragma unroll
            for (int tg = 0; tg < 4; ++tg) {
                const int lidx = (g * 4 + tg) * 4 + hi;
                const int d0 = ks * 8 + tg;          // 0..27
                s = fmaf(base[ks * 128 + lidx], xr[d0], s);
                const int d1 = d0 + 4;               // 4..31, keep d1 < 28
                if (d1 < 28)
                    s = fmaf(base[ks * 128 + lidx + 2], xr[d1], s);
            }
    }
    #pragma unroll
    for (int off = 16; off > 0; off >>= 1)
        s += __shfl_xor_sync(0xFFFFFFFFu, s, off);
    if (lane == 0)
        out[((size_t)b * COUT + o) * LOUT + 4096] = s + bias[o];
}

extern "C" void kernel_launch(void* const* d_in, const int* in_sizes, int n_in,
                              void* d_out, int out_size) {
    const float* x      = (const float*)d_in[0];  // [32,256,4096]
    const float* weight = (const float*)d_in[1];  // [256,256,7]
    const float* P      = (const float*)d_in[2];  // [256,256,7]
    const float* bias   = (const float*)d_in[3];  // [256]
    float* out          = (float*)d_out;          // [32,256,4097]

    cudaFuncSetAttribute(conv_kernel, cudaFuncAttributeMaxDynamicSharedMemorySize,
                         SMEM_TOTAL);

    prep_kernel<<<(COUT * CIN + 255) / 256, 256>>>(weight, P);

    dim3 grid(NTT, 2, 32);                         // (16, 2, 32) = 1024 CTAs
    conv_kernel<<<grid, NTHR, SMEM_TOTAL>>>(x, bias, out);

    tail_kernel<<<1024, 256>>>(x, bias, out);      // 8192 warps, one per (b,o)
}

// round 17
// speedup vs baseline: 3.8657x; 1.0516x over previous
#include <cuda_runtime.h>
#include <cstdint>

// Dcls1d as implicit GEMM on mma.sync.m16n8k8 tf32 (family-target compute_103).
//
// out[b,o,t] = bias[o] + sum_{c,d<56} dk[o][c][d]*xpad[b][c][t+d]
// GEMM: M=256(o) x N=32*4096(b,t) x K=256*56(c,d); t=4096 handled by tail.
//
// R17 == R14 (never ran; infra failed): CTA is 256 thr / 8 warps (tile
// 128M x 128N) so TWO CTAs fit per SM (2*256*124 regs = 63.5K <= 64K,
// 2*86KB smem <= 228KB). With 1 CTA/SM every per-chunk barrier/staging edge
// was exposed (tensor stuck ~75%); a co-resident CTA fills those gaps.
// Warp structure: 2(M) x 4(N) warps, warp tile 64x32, 7 k-steps,
// fragment-ordered A (one LDS.128 per m16 fragment), Hankel B via broadcast
// LDS.32 from a 192-float x-window, 3-stage cp.async, one barrier per chunk.

#define CIN   256
#define COUT  256
#define KT    7
#define LIN   4096
#define LOUT  4097
#define PADV  28
#define KS_N  7
#define MTILE 128
#define NTILE 128
#define NTT   32             // N-tiles over t (covers 0..4095)
#define XWIN  192            // 128 + 56, rounded to quads
#define NTHR  256

#define AFCH     (8 * KS_N * 128)     // floats per (mt,c) A chunk = 7168
#define AFBYTES  (AFCH * 4)           // 28672
#define XBYTES   (XWIN * 4)           // 768
#define SM_X0    (3 * AFBYTES)
#define SMEM_TOTAL (3 * AFBYTES + 3 * XBYTES)   // 88320

// [mt(2)][c(256)][B(8)][ks(7)][lane(32)][slot(4)] = 14.7 MB (L2-resident)
__device__ __align__(16) float g_Af[(size_t)2 * CIN * AFCH];

__device__ __forceinline__ uint32_t f2tf32(float f) {
    uint32_t u;
    asm("cvt.rna.tf32.f32 %0, %1;" : "=r"(u) : "f"(f));
    return u;
}
__device__ __forceinline__ uint32_t smem_u32(const void* p) {
    uint32_t a;
    asm("{ .reg .u64 t; cvta.to.shared.u64 t, %1; cvt.u32.u64 %0, t; }" : "=r"(a) : "l"(p));
    return a;
}
__device__ __forceinline__ void cp16(uint32_t dst, const void* src) {
    asm volatile("cp.async.cg.shared.global [%0], [%1], 16;" :: "r"(dst), "l"(src));
}

// ---------------- prep: dense lerped kernel -> fragment-ordered A -----------
__global__ void prep_kernel(const float* __restrict__ weight,
                            const float* __restrict__ P) {
    int n = blockIdx.x * blockDim.x + threadIdx.x;   // one thread per (o,c)
    if (n >= COUT * CIN) return;
    int o = n >> 8, c = n & 255;
    float dk[57];
    #pragma unroll
    for (int i = 0; i < 57; ++i) dk[i] = 0.0f;
    #pragma unroll
    for (int k = 0; k < KT; ++k) {
        size_t idx = ((size_t)o * CIN + c) * KT + k;
        float w   = weight[idx];
        float pos = P[idx] + (float)PADV;
        pos = fminf(fmaxf(pos, 0.0f), 55.0f);
        float lof = floorf(pos);
        float fr  = pos - lof;
        int lo = (int)lof;                    // 0..55; lo==55 -> fr==0
        dk[lo]     += w * (1.0f - fr);
        dk[lo + 1] += w * fr;
    }
    const int mt = o >> 7, m = o & 127;
    const int B = m >> 4, r = m & 15;
    const int g = r & 7, hi = r >> 3;
    float* base = g_Af + (((size_t)mt * CIN + c) * 8 + B) * (KS_N * 128);
    #pragma unroll
    for (int ks = 0; ks < KS_N; ++ks)
        #pragma unroll
        for (int tg = 0; tg < 4; ++tg) {
            const int lane = g * 4 + tg;
            base[ks * 128 + lane * 4 + hi]     = __uint_as_float(f2tf32(dk[ks * 8 + tg]));
            base[ks * 128 + lane * 4 + hi + 2] = __uint_as_float(f2tf32(dk[ks * 8 + tg + 4]));
        }
}

// ---------------- main GEMM (t in [0, 4096)) --------------------------------
__global__ void __launch_bounds__(NTHR, 2) conv_kernel(
    const float* __restrict__ x,
    const float* __restrict__ bias,
    float* __restrict__ out) {

    extern __shared__ __align__(16) char smem[];

    const int tid   = threadIdx.x;
    const int wid   = tid >> 5, lane = tid & 31;
    const int warpM = wid >> 2, warpN = wid & 3;
    const int g     = lane >> 2, tg = lane & 3;
    const int tb    = blockIdx.x * NTILE;
    const int mb    = blockIdx.y;
    const int b     = blockIdx.z;

    const float* gA = g_Af + (size_t)mb * CIN * AFCH;
    const float* xb = x + (size_t)b * CIN * LIN;

    // x-window valid range (multiples of 4: s0 = tb-28 ≡ 0 mod 4)
    const int s0 = tb - PADV;
    const int f0 = (s0 < 0) ? -s0 : 0;
    const int f1 = (LIN - s0 < XWIN) ? (LIN - s0) : XWIN;
    const int q0 = f0 >> 2, q1 = f1 >> 2;

    const uint32_t sb = smem_u32(smem);

    // pre-zero x-window boundary regions in all 3 buffers (persist)
    for (int i = tid; i < 3 * XWIN; i += NTHR) {
        int bf = i / XWIN, j = i - bf * XWIN;
        if (j < f0 || j >= f1)
            reinterpret_cast<float*>(smem + SM_X0 + bf * XBYTES)[j] = 0.0f;
    }

    auto stage = [&](int c, int bf) {
        const float4* srcA = reinterpret_cast<const float4*>(gA + (size_t)c * AFCH);
        const uint32_t dA  = sb + bf * AFBYTES;
        #pragma unroll
        for (int q = tid; q < AFCH / 4; q += NTHR)   // 7 iters
            cp16(dA + q * 16, srcA + q);
        if (tid < q1 - q0)
            cp16(sb + SM_X0 + bf * XBYTES + (q0 + tid) * 16,
                 xb + (size_t)c * LIN + s0 + (q0 + tid) * 4);
    };

    float acc[4][4][4];
    #pragma unroll
    for (int i = 0; i < 4; ++i)
        #pragma unroll
        for (int j = 0; j < 4; ++j)
            #pragma unroll
            for (int r = 0; r < 4; ++r) acc[i][j][r] = 0.0f;

    stage(0, 0);
    asm volatile("cp.async.commit_group;" ::: "memory");
    stage(1, 1);
    asm volatile("cp.async.commit_group;" ::: "memory");

    int bf = 0;                 // bf = c % 3
    for (int c = 0; c < CIN; ++c) {
        if (c + 1 < CIN)
            asm volatile("cp.async.wait_group 1;" ::: "memory");
        else
            asm volatile("cp.async.wait_group 0;" ::: "memory");
        __syncthreads();        // all warps done with compute(c-1); chunk c ready

        if (c + 2 < CIN) {
            int nb = bf + 2; if (nb >= 3) nb -= 3;
            stage(c + 2, nb);
            asm volatile("cp.async.commit_group;" ::: "memory");
        }

        const float* aw = reinterpret_cast<const float*>(smem + bf * AFBYTES)
                        + (warpM * 4) * (KS_N * 128);
        const float* xw = reinterpret_cast<const float*>(smem + SM_X0 + bf * XBYTES);

        #pragma unroll
        for (int ks = 0; ks < KS_N; ++ks) {
            uint32_t a[4][4];
            #pragma unroll
            for (int mt = 0; mt < 4; ++mt) {
                float4 f = reinterpret_cast<const float4*>(
                               aw + (mt * KS_N + ks) * 128)[lane];   // LDS.128
                a[mt][0] = __float_as_uint(f.x);
                a[mt][1] = __float_as_uint(f.y);
                a[mt][2] = __float_as_uint(f.z);
                a[mt][3] = __float_as_uint(f.w);
            }
            const int xbase = warpN * 32 + g + ks * 8 + tg;
            #pragma unroll
            for (int nt = 0; nt < 4; ++nt) {
                uint32_t b0 = __float_as_uint(xw[xbase + nt * 8]);
                uint32_t b1 = __float_as_uint(xw[xbase + nt * 8 + 4]);
                #pragma unroll
                for (int mt = 0; mt < 4; ++mt) {
                    asm volatile(
                        "mma.sync.aligned.m16n8k8.row.col.f32.tf32.tf32.f32 "
                        "{%0,%1,%2,%3}, {%4,%5,%6,%7}, {%8,%9}, {%0,%1,%2,%3};"
                        : "+f"(acc[mt][nt][0]), "+f"(acc[mt][nt][1]),
                          "+f"(acc[mt][nt][2]), "+f"(acc[mt][nt][3])
                        : "r"(a[mt][0]), "r"(a[mt][1]), "r"(a[mt][2]), "r"(a[mt][3]),
                          "r"(b0), "r"(b1));
                }
            }
        }
        if (++bf == 3) bf = 0;
    }

    // epilogue: scalar stores (LOUT odd -> rows 4B-aligned); all t <= 4095
    #pragma unroll
    for (int mt = 0; mt < 4; ++mt) {
        const int o  = mb * MTILE + warpM * 64 + mt * 16 + g;
        const float bv0 = bias[o];
        const float bv8 = bias[o + 8];
        float* r0 = out + ((size_t)b * COUT + o) * LOUT;
        float* r8 = r0 + 8 * LOUT;
        #pragma unroll
        for (int nt = 0; nt < 4; ++nt) {
            const int t = tb + warpN * 32 + nt * 8 + tg * 2;
            r0[t]     = acc[mt][nt][0] + bv0;
            r0[t + 1] = acc[mt][nt][1] + bv0;
            r8[t]     = acc[mt][nt][2] + bv8;
            r8[t + 1] = acc[mt][nt][3] + bv8;
        }
    }
}

// ---------------- tail: the single t = 4096 column --------------------------
// out[b,o,4096] = bias[o] + sum_{c, d<28} dk[o][c][d] * x[b][c][4068+d]
__global__ void __launch_bounds__(256) tail_kernel(
    const float* __restrict__ x,
    const float* __restrict__ bias,
    float* __restrict__ out) {

    const int wg   = blockIdx.x * 8 + (threadIdx.x >> 5);  // 0..8191
    const int lane = threadIdx.x & 31;
    const int b = wg >> 8, o = wg & 255;

    const int mt = o >> 7, m = o & 127;
    const int B = m >> 4, r = m & 15;
    const int g = r & 7, hi = r >> 3;

    float s = 0.0f;
    for (int c = lane; c < CIN; c += 32) {
        const float* base = g_Af + (((size_t)mt * CIN + c) * 8 + B) * (KS_N * 128);
        const float* xr   = x + ((size_t)b * CIN + c) * LIN + 4068;
        #pragma unroll
        for (int ks = 0; ks < 4; ++ks)
            #pragma unroll
            for (int tg = 0; tg < 4; ++tg) {
                const int lidx = (g * 4 + tg) * 4 + hi;
                const int d0 = ks * 8 + tg;          // 0..27
                s = fmaf(base[ks * 128 + lidx], xr[d0], s);
                const int d1 = d0 + 4;
                if (d1 < 28)
                    s = fmaf(base[ks * 128 + lidx + 2], xr[d1], s);
            }
    }
    #pragma unroll
    for (int off = 16; off > 0; off >>= 1)
        s += __shfl_xor_sync(0xFFFFFFFFu, s, off);
    if (lane == 0)
        out[((size_t)b * COUT + o) * LOUT + 4096] = s + bias[o];
}

extern "C" void kernel_launch(void* const* d_in, const int* in_sizes, int n_in,
                              void* d_out, int out_size) {
    const float* x      = (const float*)d_in[0];  // [32,256,4096]
    const float* weight = (const float*)d_in[1];  // [256,256,7]
    const float* P      = (const float*)d_in[2];  // [256,256,7]
    const float* bias   = (const float*)d_in[3];  // [256]
    float* out          = (float*)d_out;          // [32,256,4097]

    cudaFuncSetAttribute(conv_kernel, cudaFuncAttributeMaxDynamicSharedMemorySize,
                         SMEM_TOTAL);

    prep_kernel<<<(COUT * CIN + 255) / 256, 256>>>(weight, P);

    dim3 grid(NTT, 2, 32);                         // (32, 2, 32) = 2048 CTAs
    conv_kernel<<<grid, NTHR, SMEM_TOTAL>>>(x, bias, out);

    tail_kernel<<<1024, 256>>>(x, bias, out);      // one warp per (b,o)
}